// round 16
// baseline (speedup 1.0000x reference)
#include <cuda_runtime.h>

#define BATCH  4096
#define IDIM   1024
#define BOND   32
#define ODIM   512

#define NP1 128    // level-1 products (1024 cores -> 128)
#define NP2 16     // level-2 products (128 -> 16)

__device__ __align__(16) float g_P1[NP1 * BOND * BOND];
__device__ __align__(16) float g_P2[NP2 * BOND * BOND];
__device__ __align__(16) float g_w[ODIM];
__device__ unsigned g_tick = 0;   // monotonic; (t+1)%NP2==0 -> last arrival (replay-safe)

// ---------------------------------------------------------------------------
// Transposed store of a float4 covering elements 4e..4e+3 of a 32x32 matrix
// into Bt (pitch 33). Conflict-free.
// ---------------------------------------------------------------------------
__device__ __forceinline__ void transpose_store(float4 v, float* Bt, int e) {
    const int j  = e >> 3;
    const int k0 = (e & 7) * 4;
    Bt[(k0 + 0) * 33 + j] = v.x;
    Bt[(k0 + 1) * 33 + j] = v.y;
    Bt[(k0 + 2) * 33 + j] = v.z;
    Bt[(k0 + 3) * 33 + j] = v.w;
}

// ---------------------------------------------------------------------------
// Ordered product of 8 consecutive 32x32 matrices, 512 threads (16 warps).
// Warp w owns rows 2w, 2w+1; lane = output column. 4 warps/SMSP hide LDS
// latency (vs 2 with the 256-thread version). All 8 matrices are loaded
// upfront: thread t holds float4 #t and #(512+t)... of the 8192-float chunk,
// i.e. r[i] covers matrices 2i (threads 0..255) and 2i+1 (threads 256..511).
// ---------------------------------------------------------------------------
__device__ void prod8_512(const float4* __restrict__ base4, float* __restrict__ dst,
                          float* sA, float* sBt2) {
    const int t    = threadIdx.x;       // 0..511
    const int w    = t >> 5;            // 0..15
    const int lane = t & 31;

    float4 r[4];
    #pragma unroll
    for (int i = 0; i < 4; ++i) r[i] = base4[512 * i + t];

    // A = M0 (threads 0..255); Bt[1] = M1^T (threads 256..511, elem t-256)
    if (t < 256) ((float4*)sA)[t] = r[0];
    else         transpose_store(r[0], sBt2 + 1056, t & 255);
    __syncthreads();

    float acc0 = 0.f, acc1 = 0.f;

    #pragma unroll
    for (int s = 1; s < 8; ++s) {
        const float* Bt = sBt2 + (s & 1) * 1056;
        acc0 = acc1 = 0.f;

        #pragma unroll
        for (int l4 = 0; l4 < 8; ++l4) {
            const float4 a0 = *(const float4*)(sA + (2 * w + 0) * 32 + 4 * l4);
            const float4 a1 = *(const float4*)(sA + (2 * w + 1) * 32 + 4 * l4);
            const float b0 = Bt[lane * 33 + 4 * l4 + 0];
            const float b1 = Bt[lane * 33 + 4 * l4 + 1];
            const float b2 = Bt[lane * 33 + 4 * l4 + 2];
            const float b3 = Bt[lane * 33 + 4 * l4 + 3];

            acc0 = fmaf(a0.x, b0, acc0); acc0 = fmaf(a0.y, b1, acc0);
            acc0 = fmaf(a0.z, b2, acc0); acc0 = fmaf(a0.w, b3, acc0);
            acc1 = fmaf(a1.x, b0, acc1); acc1 = fmaf(a1.y, b1, acc1);
            acc1 = fmaf(a1.z, b2, acc1); acc1 = fmaf(a1.w, b3, acc1);
        }
        __syncthreads();                      // reads of sA / both Bt done
        if (s < 7) {
            sA[(2 * w + 0) * 32 + lane] = acc0;
            sA[(2 * w + 1) * 32 + lane] = acc1;
            const int m = s + 1;              // matrix to stage next
            if ((t >> 8) == (m & 1))          // the 256 threads holding M_m
                transpose_store(r[m >> 1], sBt2 + (m & 1) * 1056, t & 255);
            __syncthreads();
        }
    }

    dst[(2 * w + 0) * 32 + lane] = acc0;
    dst[(2 * w + 1) * 32 + lane] = acc1;
}

// ---------------------------------------------------------------------------
// K1: tree level 1. 128 blocks x 512 threads.
// ---------------------------------------------------------------------------
__global__ __launch_bounds__(512) void mps_tree1(const float* __restrict__ cores,
                                                 float* __restrict__ p1) {
    __shared__ float sA[BOND * BOND];
    __shared__ float sBt2[2 * 1056];
    prod8_512((const float4*)(cores + (size_t)blockIdx.x * 8 * BOND * BOND),
              p1 + (size_t)blockIdx.x * BOND * BOND, sA, sBt2);
}

// ---------------------------------------------------------------------------
// K2: tree level 2 + combine. 16 blocks x 512 threads. Last block (ticket)
// stages all 16 P2 matrices into 64KB smem, warp 0 runs the 16-step chain,
// then 512 threads compute w = v @ proj -> g_w.
// ---------------------------------------------------------------------------
__global__ __launch_bounds__(512) void mps_tree2(const float* __restrict__ p1,
                                                 float* __restrict__ p2,
                                                 const float* __restrict__ proj) {
    extern __shared__ float sP[];            // 64KB, last block only
    __shared__ float sA[BOND * BOND];
    __shared__ float sBt2[2 * 1056];
    __shared__ float sv[BOND];
    __shared__ unsigned sLast;

    const int t    = threadIdx.x;
    const int lane = t & 31;

    prod8_512((const float4*)(p1 + (size_t)blockIdx.x * 8 * BOND * BOND),
              p2 + (size_t)blockIdx.x * BOND * BOND, sA, sBt2);

    __threadfence();                          // publish this block's P2 (release)
    __syncthreads();
    if (t == 0) {
        unsigned tk = atomicAdd(&g_tick, 1u);
        sLast = ((tk + 1u) % NP2 == 0u) ? 1u : 0u;
    }
    __syncthreads();
    if (!sLast) return;
    __threadfence();                          // acquire

    // stage P2: 512 threads * 8 float4 = 64KB (L2 reads, bypass L1)
    {
        const float4* g4 = (const float4*)p2;
        float4*       s4 = (float4*)sP;
        #pragma unroll
        for (int i = 0; i < 8; ++i)
            s4[t + 512 * i] = __ldcg(g4 + t + 512 * i);
    }
    __syncthreads();

    if (t < 32) {
        float v = 1.0f;
        #pragma unroll
        for (int c = 0; c < NP2; ++c) {
            const float* P = sP + c * 1024;
            float a0 = 0.f, a1 = 0.f, a2 = 0.f, a3 = 0.f;
            #pragma unroll
            for (int j = 0; j < 8; ++j) {
                a0 = fmaf(__shfl_sync(0xffffffffu, v, j),      P[j * 32 + lane],        a0);
                a1 = fmaf(__shfl_sync(0xffffffffu, v, j + 8),  P[(j + 8) * 32 + lane],  a1);
                a2 = fmaf(__shfl_sync(0xffffffffu, v, j + 16), P[(j + 16) * 32 + lane], a2);
                a3 = fmaf(__shfl_sync(0xffffffffu, v, j + 24), P[(j + 24) * 32 + lane], a3);
            }
            v = (a0 + a1) + (a2 + a3);
        }
        sv[lane] = v;
    }
    __syncthreads();

    // w = v @ proj : one output per thread, 32 outstanding coalesced LDGs
    {
        float a0 = 0.f, a1 = 0.f, a2 = 0.f, a3 = 0.f;
        #pragma unroll
        for (int j = 0; j < 8; ++j) {
            a0 = fmaf(sv[j],      proj[(j)      * ODIM + t], a0);
            a1 = fmaf(sv[j + 8],  proj[(j + 8)  * ODIM + t], a1);
            a2 = fmaf(sv[j + 16], proj[(j + 16) * ODIM + t], a2);
            a3 = fmaf(sv[j + 24], proj[(j + 24) * ODIM + t], a3);
        }
        g_w[t] = (a0 + a1) + (a2 + a3);
    }
}

// ---------------------------------------------------------------------------
// K3: scal + output fused. 512 blocks x 256 threads, one warp per batch row.
// s_b = prod(inputs[b,:]) (8 LDG.128/lane, warp reduce); out = s*w + bias.
// g_w is tiny and L1-resident per SM after the first warp touches it.
// ---------------------------------------------------------------------------
__global__ __launch_bounds__(256) void mps_out(const float* __restrict__ inputs,
                                               const float* __restrict__ bias,
                                               float* __restrict__ out) {
    const int lane = threadIdx.x & 31;
    const int b    = blockIdx.x * 8 + (threadIdx.x >> 5);

    const float4* row = (const float4*)(inputs + (size_t)b * IDIM);
    float4 r[8];
    #pragma unroll
    for (int i = 0; i < 8; ++i) r[i] = row[lane + 32 * i];

    float p0 = (r[0].x * r[0].y) * (r[0].z * r[0].w);
    float p1 = (r[1].x * r[1].y) * (r[1].z * r[1].w);
    float p2 = (r[2].x * r[2].y) * (r[2].z * r[2].w);
    float p3 = (r[3].x * r[3].y) * (r[3].z * r[3].w);
    float p4 = (r[4].x * r[4].y) * (r[4].z * r[4].w);
    float p5 = (r[5].x * r[5].y) * (r[5].z * r[5].w);
    float p6 = (r[6].x * r[6].y) * (r[6].z * r[6].w);
    float p7 = (r[7].x * r[7].y) * (r[7].z * r[7].w);
    float p  = ((p0 * p1) * (p2 * p3)) * ((p4 * p5) * (p6 * p7));

    #pragma unroll
    for (int off = 16; off; off >>= 1)
        p *= __shfl_xor_sync(0xffffffffu, p, off);

    const float4* w4 = (const float4*)g_w;
    const float4* b4 = (const float4*)bias;
    float4*       o4 = (float4*)(out + (size_t)b * ODIM);

    #pragma unroll
    for (int i = 0; i < 4; ++i) {
        const float4 wv = w4[lane + 32 * i];
        const float4 bv = b4[lane + 32 * i];
        float4 ov;
        ov.x = fmaf(p, wv.x, bv.x);
        ov.y = fmaf(p, wv.y, bv.y);
        ov.z = fmaf(p, wv.z, bv.z);
        ov.w = fmaf(p, wv.w, bv.w);
        o4[lane + 32 * i] = ov;
    }
}

// ---------------------------------------------------------------------------
extern "C" void kernel_launch(void* const* d_in, const int* in_sizes, int n_in,
                              void* d_out, int out_size) {
    const float* inputs = (const float*)d_in[0];
    const float* cores  = (const float*)d_in[1];
    const float* proj   = (const float*)d_in[2];
    const float* bias   = (const float*)d_in[3];
    float* out = (float*)d_out;

    float* p1; cudaGetSymbolAddress((void**)&p1, g_P1);
    float* p2; cudaGetSymbolAddress((void**)&p2, g_P2);

    cudaFuncSetAttribute(mps_tree2,
                         cudaFuncAttributeMaxDynamicSharedMemorySize, 65536);

    mps_tree1<<<NP1, 512>>>(cores, p1);            // 1024 -> 128
    mps_tree2<<<NP2, 512, 65536>>>(p1, p2, proj);  // 128 -> 16, last block -> g_w
    mps_out  <<<BATCH / 8, 256>>>(inputs, bias, out);
}

// round 17
// speedup vs baseline: 1.0594x; 1.0594x over previous
#include <cuda_runtime.h>

#define BATCH  4096
#define IDIM   1024
#define BOND   32
#define ODIM   512

#define NP1 128    // level-1 products (1024 cores -> 128)
#define NP2 16     // level-2 products (128 -> 16)

__device__ __align__(16) float g_P1[NP1 * BOND * BOND];
__device__ __align__(16) float g_P2[NP2 * BOND * BOND];
__device__ __align__(16) float g_w[ODIM];
__device__ unsigned g_tick = 0;   // monotonic; (t+1)%NP2==0 -> last arrival (replay-safe)

// ---------------------------------------------------------------------------
// Transposed store of a float4 covering elements 4e..4e+3 of a 32x32 matrix
// into Bt (pitch 33): Bt[c*33 + r] = M[r][c]. Conflict-free.
// ---------------------------------------------------------------------------
__device__ __forceinline__ void transpose_store(float4 v, float* Bt, int e) {
    const int j  = e >> 3;          // row
    const int k0 = (e & 7) * 4;     // first col
    Bt[(k0 + 0) * 33 + j] = v.x;
    Bt[(k0 + 1) * 33 + j] = v.y;
    Bt[(k0 + 2) * 33 + j] = v.z;
    Bt[(k0 + 3) * 33 + j] = v.w;
}

// ---------------------------------------------------------------------------
// Ordered product of 8 matrices via PAIRWISE TREE inside one 512-thread block:
//   level A: Q0=M0@M1, Q1=M2@M3, Q2=M4@M5, Q3=M6@M7   (4 parallel matmuls)
//   level B: R0=Q0@Q1, R1=Q2@Q3                        (2 parallel matmuls)
//   level C: P = R0@R1                                  -> dst (row-major)
// Depth 3 (vs 7 serial) and 4x/2x per-step parallelism -> pipes stay fed.
// Row-major operands in sRow, transposed ("B") operands in sTr (pitch 33).
// ---------------------------------------------------------------------------
__device__ void prod8_tree(const float4* __restrict__ base4,
                           float* __restrict__ dst,
                           float (*sRow)[1024], float (*sTr)[1056]) {
    const int t    = threadIdx.x;   // 0..511
    const int w    = t >> 5;        // 0..15
    const int lane = t & 31;

    // ---- stage: thread t holds element (t&255) of matrices {2i + (t>=256)} ----
    float4 r[4];
    #pragma unroll
    for (int i = 0; i < 4; ++i) r[i] = base4[512 * i + t];

    const int e = t & 255;
    if (t < 256) {                         // even matrices, row-major
        #pragma unroll
        for (int i = 0; i < 4; ++i) ((float4*)sRow[i])[e] = r[i];
    } else {                               // odd matrices, transposed
        #pragma unroll
        for (int i = 0; i < 4; ++i) transpose_store(r[i], sTr[i], e);
    }
    __syncthreads();

    // ---- level A: group g = w>>2 (4 warps), 8 rows/warp, 8 accs/thread ----
    {
        const int g  = w >> 2;
        const int wq = w & 3;
        const float* A = sRow[g];
        const float* B = sTr[g];
        float acc[8];
        #pragma unroll
        for (int i = 0; i < 8; ++i) acc[i] = 0.f;

        #pragma unroll
        for (int l4 = 0; l4 < 8; ++l4) {
            const float b0 = B[lane * 33 + 4 * l4 + 0];
            const float b1 = B[lane * 33 + 4 * l4 + 1];
            const float b2 = B[lane * 33 + 4 * l4 + 2];
            const float b3 = B[lane * 33 + 4 * l4 + 3];
            #pragma unroll
            for (int rr = 0; rr < 8; ++rr) {
                const float4 a = *(const float4*)(A + (8 * wq + rr) * 32 + 4 * l4);
                acc[rr] = fmaf(a.x, b0, acc[rr]);
                acc[rr] = fmaf(a.y, b1, acc[rr]);
                acc[rr] = fmaf(a.z, b2, acc[rr]);
                acc[rr] = fmaf(a.w, b3, acc[rr]);
            }
        }
        __syncthreads();                    // all level-A reads complete

        // Q0 -> sRow[0] (row-major), Q1 -> sTr[0] (transposed),
        // Q2 -> sRow[1],             Q3 -> sTr[1]
        if (g == 0) {
            #pragma unroll
            for (int rr = 0; rr < 8; ++rr) sRow[0][(8 * wq + rr) * 32 + lane] = acc[rr];
        } else if (g == 1) {
            #pragma unroll
            for (int rr = 0; rr < 8; ++rr) sTr[0][lane * 33 + 8 * wq + rr] = acc[rr];
        } else if (g == 2) {
            #pragma unroll
            for (int rr = 0; rr < 8; ++rr) sRow[1][(8 * wq + rr) * 32 + lane] = acc[rr];
        } else {
            #pragma unroll
            for (int rr = 0; rr < 8; ++rr) sTr[1][lane * 33 + 8 * wq + rr] = acc[rr];
        }
    }
    __syncthreads();

    // ---- level B: group h = w>>3 (8 warps), 4 rows/warp, 4 accs/thread ----
    {
        const int h  = w >> 3;
        const int wh = w & 7;
        const float* A = sRow[h];
        const float* B = sTr[h];
        float acc[4];
        #pragma unroll
        for (int i = 0; i < 4; ++i) acc[i] = 0.f;

        #pragma unroll
        for (int l4 = 0; l4 < 8; ++l4) {
            const float b0 = B[lane * 33 + 4 * l4 + 0];
            const float b1 = B[lane * 33 + 4 * l4 + 1];
            const float b2 = B[lane * 33 + 4 * l4 + 2];
            const float b3 = B[lane * 33 + 4 * l4 + 3];
            #pragma unroll
            for (int rr = 0; rr < 4; ++rr) {
                const float4 a = *(const float4*)(A + (4 * wh + rr) * 32 + 4 * l4);
                acc[rr] = fmaf(a.x, b0, acc[rr]);
                acc[rr] = fmaf(a.y, b1, acc[rr]);
                acc[rr] = fmaf(a.z, b2, acc[rr]);
                acc[rr] = fmaf(a.w, b3, acc[rr]);
            }
        }
        __syncthreads();                    // all level-B reads complete

        // R0 -> sRow[2] (row-major), R1 -> sTr[2] (transposed)
        if (h == 0) {
            #pragma unroll
            for (int rr = 0; rr < 4; ++rr) sRow[2][(4 * wh + rr) * 32 + lane] = acc[rr];
        } else {
            #pragma unroll
            for (int rr = 0; rr < 4; ++rr) sTr[2][lane * 33 + 4 * wh + rr] = acc[rr];
        }
    }
    __syncthreads();

    // ---- level C: 16 warps, 2 rows/warp, 2 accs/thread -> dst ----
    {
        const float* A = sRow[2];
        const float* B = sTr[2];
        float acc0 = 0.f, acc1 = 0.f;

        #pragma unroll
        for (int l4 = 0; l4 < 8; ++l4) {
            const float b0 = B[lane * 33 + 4 * l4 + 0];
            const float b1 = B[lane * 33 + 4 * l4 + 1];
            const float b2 = B[lane * 33 + 4 * l4 + 2];
            const float b3 = B[lane * 33 + 4 * l4 + 3];
            const float4 a0 = *(const float4*)(A + (2 * w + 0) * 32 + 4 * l4);
            const float4 a1 = *(const float4*)(A + (2 * w + 1) * 32 + 4 * l4);
            acc0 = fmaf(a0.x, b0, acc0); acc0 = fmaf(a0.y, b1, acc0);
            acc0 = fmaf(a0.z, b2, acc0); acc0 = fmaf(a0.w, b3, acc0);
            acc1 = fmaf(a1.x, b0, acc1); acc1 = fmaf(a1.y, b1, acc1);
            acc1 = fmaf(a1.z, b2, acc1); acc1 = fmaf(a1.w, b3, acc1);
        }
        dst[(2 * w + 0) * 32 + lane] = acc0;
        dst[(2 * w + 1) * 32 + lane] = acc1;
    }
}

// ---------------------------------------------------------------------------
// K1: tree level 1. 128 blocks x 512 threads.
// ---------------------------------------------------------------------------
__global__ __launch_bounds__(512) void mps_tree1(const float* __restrict__ cores,
                                                 float* __restrict__ p1) {
    __shared__ float sRow[4][1024];
    __shared__ float sTr[4][1056];
    prod8_tree((const float4*)(cores + (size_t)blockIdx.x * 8 * BOND * BOND),
               p1 + (size_t)blockIdx.x * BOND * BOND, sRow, sTr);
}

// ---------------------------------------------------------------------------
// K2: tree level 2 + combine. 16 blocks x 512 threads. Last block (ticket)
// stages all 16 P2 matrices into 64KB dynamic smem, warp 0 runs the 16-step
// chain, then 512 threads compute w = v @ proj -> g_w.
// ---------------------------------------------------------------------------
__global__ __launch_bounds__(512) void mps_tree2(const float* __restrict__ p1,
                                                 float* __restrict__ p2,
                                                 const float* __restrict__ proj) {
    extern __shared__ float sP[];            // 64KB, last block only
    __shared__ float sRow[4][1024];
    __shared__ float sTr[4][1056];
    __shared__ float sv[BOND];
    __shared__ unsigned sLast;

    const int t    = threadIdx.x;
    const int lane = t & 31;

    prod8_tree((const float4*)(p1 + (size_t)blockIdx.x * 8 * BOND * BOND),
               p2 + (size_t)blockIdx.x * BOND * BOND, sRow, sTr);

    __threadfence();                          // publish this block's P2 (release)
    __syncthreads();
    if (t == 0) {
        unsigned tk = atomicAdd(&g_tick, 1u);
        sLast = ((tk + 1u) % NP2 == 0u) ? 1u : 0u;
    }
    __syncthreads();
    if (!sLast) return;
    __threadfence();                          // acquire

    // stage P2: 512 threads * 8 float4 = 64KB (L2 reads, bypass L1)
    {
        const float4* g4 = (const float4*)p2;
        float4*       s4 = (float4*)sP;
        #pragma unroll
        for (int i = 0; i < 8; ++i)
            s4[t + 512 * i] = __ldcg(g4 + t + 512 * i);
    }
    __syncthreads();

    if (t < 32) {
        float v = 1.0f;
        #pragma unroll
        for (int c = 0; c < NP2; ++c) {
            const float* P = sP + c * 1024;
            float a0 = 0.f, a1 = 0.f, a2 = 0.f, a3 = 0.f;
            #pragma unroll
            for (int j = 0; j < 8; ++j) {
                a0 = fmaf(__shfl_sync(0xffffffffu, v, j),      P[j * 32 + lane],        a0);
                a1 = fmaf(__shfl_sync(0xffffffffu, v, j + 8),  P[(j + 8) * 32 + lane],  a1);
                a2 = fmaf(__shfl_sync(0xffffffffu, v, j + 16), P[(j + 16) * 32 + lane], a2);
                a3 = fmaf(__shfl_sync(0xffffffffu, v, j + 24), P[(j + 24) * 32 + lane], a3);
            }
            v = (a0 + a1) + (a2 + a3);
        }
        sv[lane] = v;
    }
    __syncthreads();

    // w = v @ proj : one output per thread, 32 outstanding coalesced LDGs
    {
        float a0 = 0.f, a1 = 0.f, a2 = 0.f, a3 = 0.f;
        #pragma unroll
        for (int j = 0; j < 8; ++j) {
            a0 = fmaf(sv[j],      proj[(j)      * ODIM + t], a0);
            a1 = fmaf(sv[j + 8],  proj[(j + 8)  * ODIM + t], a1);
            a2 = fmaf(sv[j + 16], proj[(j + 16) * ODIM + t], a2);
            a3 = fmaf(sv[j + 24], proj[(j + 24) * ODIM + t], a3);
        }
        g_w[t] = (a0 + a1) + (a2 + a3);
    }
}

// ---------------------------------------------------------------------------
// K3: scal + output fused. 512 blocks x 256 threads, one warp per batch row.
// ---------------------------------------------------------------------------
__global__ __launch_bounds__(256) void mps_out(const float* __restrict__ inputs,
                                               const float* __restrict__ bias,
                                               float* __restrict__ out) {
    const int lane = threadIdx.x & 31;
    const int b    = blockIdx.x * 8 + (threadIdx.x >> 5);

    const float4* row = (const float4*)(inputs + (size_t)b * IDIM);
    float4 r[8];
    #pragma unroll
    for (int i = 0; i < 8; ++i) r[i] = row[lane + 32 * i];

    float p0 = (r[0].x * r[0].y) * (r[0].z * r[0].w);
    float p1 = (r[1].x * r[1].y) * (r[1].z * r[1].w);
    float p2 = (r[2].x * r[2].y) * (r[2].z * r[2].w);
    float p3 = (r[3].x * r[3].y) * (r[3].z * r[3].w);
    float p4 = (r[4].x * r[4].y) * (r[4].z * r[4].w);
    float p5 = (r[5].x * r[5].y) * (r[5].z * r[5].w);
    float p6 = (r[6].x * r[6].y) * (r[6].z * r[6].w);
    float p7 = (r[7].x * r[7].y) * (r[7].z * r[7].w);
    float p  = ((p0 * p1) * (p2 * p3)) * ((p4 * p5) * (p6 * p7));

    #pragma unroll
    for (int off = 16; off; off >>= 1)
        p *= __shfl_xor_sync(0xffffffffu, p, off);

    const float4* w4 = (const float4*)g_w;
    const float4* b4 = (const float4*)bias;
    float4*       o4 = (float4*)(out + (size_t)b * ODIM);

    #pragma unroll
    for (int i = 0; i < 4; ++i) {
        const float4 wv = w4[lane + 32 * i];
        const float4 bv = b4[lane + 32 * i];
        float4 ov;
        ov.x = fmaf(p, wv.x, bv.x);
        ov.y = fmaf(p, wv.y, bv.y);
        ov.z = fmaf(p, wv.z, bv.z);
        ov.w = fmaf(p, wv.w, bv.w);
        o4[lane + 32 * i] = ov;
    }
}

// ---------------------------------------------------------------------------
extern "C" void kernel_launch(void* const* d_in, const int* in_sizes, int n_in,
                              void* d_out, int out_size) {
    const float* inputs = (const float*)d_in[0];
    const float* cores  = (const float*)d_in[1];
    const float* proj   = (const float*)d_in[2];
    const float* bias   = (const float*)d_in[3];
    float* out = (float*)d_out;

    float* p1; cudaGetSymbolAddress((void**)&p1, g_P1);
    float* p2; cudaGetSymbolAddress((void**)&p2, g_P2);

    cudaFuncSetAttribute(mps_tree2,
                         cudaFuncAttributeMaxDynamicSharedMemorySize, 65536);

    mps_tree1<<<NP1, 512>>>(cores, p1);            // 1024 -> 128
    mps_tree2<<<NP2, 512, 65536>>>(p1, p2, proj);  // 128 -> 16, last block -> g_w
    mps_out  <<<BATCH / 8, 256>>>(inputs, bias, out);
}